// round 1
// baseline (speedup 1.0000x reference)
#include <cuda_runtime.h>
#include <math.h>

// Problem dims (hardcoded from reference setup_inputs)
#define B_SZ 512
#define T_IN 1125          // input time length
#define E_SZ 5             // electrodes
#define C_SZ 40            // channels
#define L_SZ 216           // pooled length: (1101-25)/5+1
#define G_SZ 40            // 4*H gates
#define H_SZ 10
#define KK   125           // 25 taps * 5 electrodes
#define XG_STRIDE (B_SZ*G_SZ)   // 20480 floats per timestep

// ---- scratch (no cudaMalloc allowed) ----
__device__ __align__(16) float d_Wcomb[KK*G_SZ];          // [kk][g], kk = 5k+e
__device__ __align__(16) float d_bg[G_SZ];
__device__ __align__(16) float d_xg[L_SZ*B_SZ*G_SZ];      // [t][b][g]

// ============================================================
// Kernel 0: fold conv_time, conv_spat, BN, avgpool(1/25), w_ih,
// and all biases into Wcomb[40][125] + bg[40].
// ============================================================
__global__ void prep_kernel(const float* __restrict__ wt,     // conv_time_w [40][25]
                            const float* __restrict__ tb,     // conv_time_b [40]
                            const float* __restrict__ ws,     // conv_spat_w [40][40][5]
                            const float* __restrict__ gamma,
                            const float* __restrict__ beta,
                            const float* __restrict__ mean,
                            const float* __restrict__ var,
                            const float* __restrict__ wih,    // [40][40]
                            const float* __restrict__ bih,
                            const float* __restrict__ bhh)
{
    __shared__ float scale_s[C_SZ], shift_s[C_SZ], cb_s[C_SZ];
    __shared__ float A_s[G_SZ*C_SZ*E_SZ];   // [g][c'][e] = w_ih*scale*w_spat, 8000 floats
    int t = threadIdx.x;
    if (t < C_SZ) {
        float sc = gamma[t] * rsqrtf(var[t] + 1e-5f);
        scale_s[t] = sc;
        shift_s[t] = beta[t] - mean[t]*sc;
        float cb = 0.f;
        for (int cp = 0; cp < C_SZ; cp++) {
            float s5 = 0.f;
            #pragma unroll
            for (int e = 0; e < E_SZ; e++) s5 += ws[(t*C_SZ+cp)*E_SZ+e];
            cb += tb[cp]*s5;
        }
        cb_s[t] = cb;   // spat applied to time-bias, per channel c
    }
    __syncthreads();
    // A[g][c'][e] = sum_c wih[g,c]*scale[c]*ws[c,c',e]
    for (int o = t; o < G_SZ*C_SZ*E_SZ; o += blockDim.x) {
        int g = o / (C_SZ*E_SZ);
        int rem = o % (C_SZ*E_SZ);
        int cp = rem / E_SZ, e = rem % E_SZ;
        float s = 0.f;
        for (int c = 0; c < C_SZ; c++)
            s += wih[g*C_SZ+c]*scale_s[c]*ws[(c*C_SZ+cp)*E_SZ+e];
        A_s[o] = s;
    }
    __syncthreads();
    // Wcomb[(5k+e)*40+g] = (1/25) * sum_c' A[g][c'][e] * wt[c'][k]
    for (int o = t; o < KK*G_SZ; o += blockDim.x) {
        int g = o % G_SZ;
        int kk = o / G_SZ;
        int k = kk / E_SZ, e = kk % E_SZ;
        float s = 0.f;
        for (int cp = 0; cp < C_SZ; cp++)
            s += A_s[(g*C_SZ+cp)*E_SZ+e] * wt[cp*25+k];
        d_Wcomb[o] = s * (1.0f/25.0f);
    }
    if (t < G_SZ) {
        float s = bih[t] + bhh[t];
        for (int c = 0; c < C_SZ; c++)
            s += wih[t*C_SZ+c]*(scale_s[c]*cb_s[c] + shift_s[c]);
        d_bg[t] = s;
    }
}

// ============================================================
// Kernel 1: box-filter + fused conv/pool/GEMM -> xg[t][b][g]
// grid (2 halves, 512 batches), block (10 gate-groups, 25 p-rows)
// Each CTA: one (b, half): p_local in [0,108), 125-float contiguous
// patches of Bsum, 4 gates x 5 p per thread.
// ============================================================
__global__ void __launch_bounds__(250) conv_kernel(const float* __restrict__ x)
{
    __shared__ float xs[2920];                    // x slab
    __shared__ float Bs[3232];                    // box sums [560 t][5 e] (+pad)
    __shared__ __align__(16) float Ws[KK*G_SZ];   // Wcomb [kk][40]
    int half = blockIdx.x;
    int b    = blockIdx.y;
    int gx = threadIdx.x;                // 0..9 -> gates 4gx..4gx+3
    int py = threadIdx.y;                // 0..24
    int ti = gx + 10*py;                 // 0..249

    const float* xb = x + (size_t)b*(T_IN*E_SZ) + half*2700;
    for (int i = ti; i < 2920; i += 250) xs[i] = xb[i];
    for (int i = ti; i < KK*G_SZ; i += 250) Ws[i] = d_Wcomb[i];
    __syncthreads();

    // sliding box sums: Bs[t*5+e] = sum_{j<25} xs[(t+j)*5+e], t in [0,560)
    {
        int e = ti % 5, seg = ti / 5;
        int t0 = seg*12;
        if (t0 < 560) {
            int t1 = min(t0+12, 560);
            float s = 0.f;
            #pragma unroll
            for (int j = 0; j < 25; j++) s += xs[(t0+j)*5 + e];
            Bs[t0*5+e] = s;
            for (int tt = t0+1; tt < t1; tt++) {
                s += xs[(tt+24)*5+e] - xs[(tt-1)*5+e];
                Bs[tt*5+e] = s;
            }
        }
    }
    __syncthreads();

    float acc[4][5];
    {
        const float4 bg4 = *(const float4*)&d_bg[4*gx];
        #pragma unroll
        for (int j = 0; j < 5; j++) {
            acc[0][j] = bg4.x; acc[1][j] = bg4.y; acc[2][j] = bg4.z; acc[3][j] = bg4.w;
        }
    }
    int pb[5];
    #pragma unroll
    for (int j = 0; j < 5; j++) pb[j] = 25*(py + 25*j);

    #pragma unroll 5
    for (int kk = 0; kk < KK; kk++) {
        const float4 w = *(const float4*)&Ws[kk*G_SZ + 4*gx];
        #pragma unroll
        for (int j = 0; j < 5; j++) {
            float xv = Bs[pb[j] + kk];
            acc[0][j] = fmaf(w.x, xv, acc[0][j]);
            acc[1][j] = fmaf(w.y, xv, acc[1][j]);
            acc[2][j] = fmaf(w.z, xv, acc[2][j]);
            acc[3][j] = fmaf(w.w, xv, acc[3][j]);
        }
    }

    int pbase = half*108;
    #pragma unroll
    for (int j = 0; j < 5; j++) {
        int pl = py + 25*j;
        if (pl < 108) {
            float4 v = make_float4(acc[0][j], acc[1][j], acc[2][j], acc[3][j]);
            *(float4*)&d_xg[(size_t)(pbase+pl)*XG_STRIDE + b*G_SZ + 4*gx] = v;
        }
    }
}

// ============================================================
// Kernel 2: LSTM scan (216 steps) + final FC.
// One warp per batch element; lane l<20 owns gates l and l+20.
// Gate order (torch): [0:10)=i, [10:20)=f, [20:30)=g, [30:40)=o.
//  -> act1 = sigmoid (i or f), act2 = tanh (g, lanes<10) / sigmoid (o).
// ============================================================
__device__ __forceinline__ float sigf(float xv) {
    return __fdividef(1.0f, 1.0f + __expf(-xv));
}

__global__ void __launch_bounds__(256) lstm_kernel(const float* __restrict__ whh,  // [40][10]
                                                   const float* __restrict__ fcw,  // [2][10]
                                                   const float* __restrict__ fcb,  // [2]
                                                   float* __restrict__ out)
{
    int warp = threadIdx.x >> 5;
    int lid  = threadIdx.x & 31;
    int b    = blockIdx.x*8 + warp;

    int r = min(lid, 19);
    float wa[H_SZ], wb[H_SZ];
    #pragma unroll
    for (int j = 0; j < H_SZ; j++) {
        wa[j] = whh[r*H_SZ + j];
        wb[j] = whh[(r+20)*H_SZ + j];
    }
    // act2 params: lanes<10 -> tanh = 2*sig(2x)-1 ; lanes 10..19 -> sigmoid
    const float scf = (lid < 10) ? 2.f : 1.f;
    const float k1f = (lid < 10) ? 2.f : 1.f;
    const float k0f = (lid < 10) ? -1.f : 0.f;

    float h[H_SZ];
    #pragma unroll
    for (int j = 0; j < H_SZ; j++) h[j] = 0.f;
    float c = 0.f;

    const float* xp = d_xg + (size_t)b*G_SZ + r;
    float p1 = __ldg(xp);
    float p2 = __ldg(xp + 20);

    for (int t = 0; t < L_SZ; t++) {
        float cur1 = p1, cur2 = p2;
        if (t < L_SZ-1) {                        // prefetch next step
            const float* nx = xp + (size_t)(t+1)*XG_STRIDE;
            p1 = __ldg(nx);
            p2 = __ldg(nx + 20);
        }
        float g1 = cur1, g2 = cur2;
        #pragma unroll
        for (int j = 0; j < H_SZ; j++) {
            g1 = fmaf(wa[j], h[j], g1);
            g2 = fmaf(wb[j], h[j], g2);
        }
        float a1 = sigf(g1);                         // i (l<10) / f (10..19)
        float a2 = fmaf(k1f, sigf(scf*g2), k0f);     // g (l<10) / o (10..19)
        float fv = __shfl_sync(0xffffffffu, a1, lid + 10);
        float ov = __shfl_sync(0xffffffffu, a2, lid + 10);
        c = fmaf(fv, c, a1*a2);                      // c = f*c + i*g (lanes<10)
        float e2 = __expf(-2.f*c);
        float tc = __fdividef(1.f - e2, 1.f + e2);   // tanh(c)
        float hv = ov*tc;
        #pragma unroll
        for (int j = 0; j < H_SZ; j++)
            h[j] = __shfl_sync(0xffffffffu, hv, j);
    }

    if (lid < 2) {
        float o = fcb[lid];
        #pragma unroll
        for (int j = 0; j < H_SZ; j++) o = fmaf(fcw[lid*H_SZ + j], h[j], o);
        out[b*2 + lid] = o;
    }
}

// ============================================================
extern "C" void kernel_launch(void* const* d_in, const int* in_sizes, int n_in,
                              void* d_out, int out_size)
{
    const float* x     = (const float*)d_in[0];
    const float* ctw   = (const float*)d_in[1];
    const float* ctb   = (const float*)d_in[2];
    const float* csw   = (const float*)d_in[3];
    const float* gamma = (const float*)d_in[4];
    const float* beta  = (const float*)d_in[5];
    const float* mean  = (const float*)d_in[6];
    const float* var   = (const float*)d_in[7];
    const float* wih   = (const float*)d_in[8];
    const float* whh   = (const float*)d_in[9];
    const float* bih   = (const float*)d_in[10];
    const float* bhh   = (const float*)d_in[11];
    const float* fcw   = (const float*)d_in[12];
    const float* fcb   = (const float*)d_in[13];
    float* out = (float*)d_out;

    prep_kernel<<<1, 512>>>(ctw, ctb, csw, gamma, beta, mean, var, wih, bih, bhh);
    conv_kernel<<<dim3(2, B_SZ), dim3(10, 25)>>>(x);
    lstm_kernel<<<B_SZ/8, 256>>>(whh, fcw, fcb, out);
}

// round 2
// speedup vs baseline: 1.3499x; 1.3499x over previous
#include <cuda_runtime.h>
#include <math.h>

// Problem dims (hardcoded from reference setup_inputs)
#define B_SZ 512
#define T_IN 1125
#define E_SZ 5
#define C_SZ 40
#define L_SZ 216
#define G_SZ 40
#define H_SZ 10
#define KK   125
#define XG_STRIDE (B_SZ*G_SZ)

#define PREP_CTAS 8
#define GPC 5   // gates per prep CTA

// ---- scratch (no cudaMalloc allowed) ----
__device__ __align__(16) float d_Wcomb[KK*G_SZ];          // [kk][g]
__device__ __align__(16) float d_bg[G_SZ];
__device__ __align__(16) float d_xg[L_SZ*B_SZ*G_SZ];      // [t][b][g]

// ============================================================
// packed f32x2 helpers
// ============================================================
__device__ __forceinline__ unsigned long long pack2(float lo, float hi) {
    unsigned long long r;
    asm("mov.b64 %0, {%1, %2};" : "=l"(r) : "f"(lo), "f"(hi));
    return r;
}
__device__ __forceinline__ void ffma2(unsigned long long& d,
                                      unsigned long long a,
                                      unsigned long long b) {
    asm("fma.rn.f32x2 %0, %1, %2, %0;" : "+l"(d) : "l"(a), "l"(b));
}
__device__ __forceinline__ float2 unpack2(unsigned long long v) {
    float2 r;
    asm("mov.b64 {%0, %1}, %2;" : "=f"(r.x), "=f"(r.y) : "l"(v));
    return r;
}
__device__ __forceinline__ float tanh_a(float x) {
    float r; asm("tanh.approx.f32 %0, %1;" : "=f"(r) : "f"(x)); return r;
}

// ============================================================
// Kernel 0: fold conv_time, conv_spat, BN, avgpool, w_ih, biases
// into Wcomb[125][40] + bg[40].  8 CTAs, 5 gates each; all math
// from shared memory, fully parallel.
// ============================================================
__global__ void __launch_bounds__(256) prep_kernel(
        const float* __restrict__ wt,     // [40][25]
        const float* __restrict__ tb,     // [40]
        const float* __restrict__ ws,     // [40][40][5]
        const float* __restrict__ gamma,
        const float* __restrict__ beta,
        const float* __restrict__ mean,
        const float* __restrict__ var,
        const float* __restrict__ wih,    // [40][40]
        const float* __restrict__ bih,
        const float* __restrict__ bhh)
{
    __shared__ float s_wt[C_SZ*25];
    __shared__ float s_ws[C_SZ*C_SZ*E_SZ];
    __shared__ float s_wih[G_SZ*C_SZ];
    __shared__ float s_tb[C_SZ], s_scale[C_SZ], s_shift[C_SZ], s_cb[C_SZ];
    __shared__ float A_s[GPC*C_SZ*E_SZ];   // [g_local][cp][e]

    int t  = threadIdx.x;
    int g0 = blockIdx.x * GPC;

    for (int i = t; i < C_SZ*25;        i += 256) s_wt[i]  = wt[i];
    for (int i = t; i < C_SZ*C_SZ*E_SZ; i += 256) s_ws[i]  = ws[i];
    for (int i = t; i < G_SZ*C_SZ;      i += 256) s_wih[i] = wih[i];
    if (t < C_SZ) {
        s_tb[t] = tb[t];
        float sc = gamma[t] * rsqrtf(var[t] + 1e-5f);
        s_scale[t] = sc;
        s_shift[t] = beta[t] - mean[t]*sc;
    }
    __syncthreads();

    // cb[c] = sum_cp tb[cp] * sum_e ws[c,cp,e]   (parallel over (c, cp-chunk))
    if (t < C_SZ) {
        float cb = 0.f;
        for (int cp = 0; cp < C_SZ; cp++) {
            float s5 = 0.f;
            #pragma unroll
            for (int e = 0; e < E_SZ; e++) s5 += s_ws[(t*C_SZ+cp)*E_SZ+e];
            cb += s_tb[cp]*s5;
        }
        s_cb[t] = cb;
    }
    // A[gl][cp][e] = sum_c wih[g0+gl,c]*scale[c]*ws[c,cp,e]
    for (int o = t; o < GPC*C_SZ*E_SZ; o += 256) {
        int gl = o / (C_SZ*E_SZ);
        int rem = o % (C_SZ*E_SZ);
        int cp = rem / E_SZ, e = rem % E_SZ;
        const float* wr = &s_wih[(g0+gl)*C_SZ];
        float s = 0.f;
        #pragma unroll 8
        for (int c = 0; c < C_SZ; c++)
            s += wr[c]*s_scale[c]*s_ws[(c*C_SZ+cp)*E_SZ+e];
        A_s[o] = s;
    }
    __syncthreads();

    // Wcomb[(5k+e)*40 + g0+gl] = (1/25) sum_cp A[gl][cp][e] * wt[cp][k]
    for (int o = t; o < KK*GPC; o += 256) {
        int gl = o % GPC;
        int kk = o / GPC;
        int k = kk / E_SZ, e = kk % E_SZ;
        float s = 0.f;
        #pragma unroll 8
        for (int cp = 0; cp < C_SZ; cp++)
            s += A_s[(gl*C_SZ+cp)*E_SZ+e] * s_wt[cp*25+k];
        d_Wcomb[kk*G_SZ + g0 + gl] = s * (1.0f/25.0f);
    }
    if (t < GPC) {
        int g = g0 + t;
        float s = bih[g] + bhh[g];
        for (int c = 0; c < C_SZ; c++)
            s += s_wih[g*C_SZ+c]*(s_scale[c]*s_cb[c] + s_shift[c]);
        d_bg[g] = s;
    }
}

// ============================================================
// Kernel 1: box-filter + fused conv/pool/GEMM -> xg[t][b][g]
// packed fma.rn.f32x2 over gate pairs.
// ============================================================
__global__ void __launch_bounds__(250) conv_kernel(const float* __restrict__ x)
{
    __shared__ float xs[2920];
    __shared__ float Bs[2800];
    __shared__ __align__(16) float Ws[KK*G_SZ];
    int half = blockIdx.x;
    int b    = blockIdx.y;
    int gx = threadIdx.x;                // 0..9 -> gates 4gx..4gx+3
    int py = threadIdx.y;                // 0..24
    int ti = gx + 10*py;

    const float* xb = x + (size_t)b*(T_IN*E_SZ) + half*2700;
    for (int i = ti; i < 2920; i += 250) xs[i] = xb[i];
    for (int i = ti; i < KK*G_SZ; i += 250) Ws[i] = d_Wcomb[i];
    __syncthreads();

    // sliding box sums: Bs[t*5+e] = sum_{j<25} xs[(t+j)*5+e], t in [0,560)
    {
        int e = ti % 5, seg = ti / 5;
        int t0 = seg*12;
        if (t0 < 560) {
            int t1 = min(t0+12, 560);
            float s = 0.f;
            #pragma unroll
            for (int j = 0; j < 25; j++) s += xs[(t0+j)*5 + e];
            Bs[t0*5+e] = s;
            for (int tt = t0+1; tt < t1; tt++) {
                s += xs[(tt+24)*5+e] - xs[(tt-1)*5+e];
                Bs[tt*5+e] = s;
            }
        }
    }
    __syncthreads();

    unsigned long long acc0[5], acc1[5];   // gate pairs (4gx,4gx+1) and (4gx+2,4gx+3)
    {
        const float4 bg4 = *(const float4*)&d_bg[4*gx];
        unsigned long long b0 = pack2(bg4.x, bg4.y);
        unsigned long long b1 = pack2(bg4.z, bg4.w);
        #pragma unroll
        for (int j = 0; j < 5; j++) { acc0[j] = b0; acc1[j] = b1; }
    }
    int pb[5];
    #pragma unroll
    for (int j = 0; j < 5; j++) pb[j] = 25*(py + 25*j);

    #pragma unroll 5
    for (int kk = 0; kk < KK; kk++) {
        const float4 w = *(const float4*)&Ws[kk*G_SZ + 4*gx];
        unsigned long long wp0 = pack2(w.x, w.y);
        unsigned long long wp1 = pack2(w.z, w.w);
        #pragma unroll
        for (int j = 0; j < 5; j++) {
            float xv = Bs[pb[j] + kk];
            unsigned long long xp = pack2(xv, xv);
            ffma2(acc0[j], wp0, xp);
            ffma2(acc1[j], wp1, xp);
        }
    }

    int pbase = half*108;
    #pragma unroll
    for (int j = 0; j < 5; j++) {
        int pl = py + 25*j;
        if (pl < 108) {
            float2 lo = unpack2(acc0[j]);
            float2 hi = unpack2(acc1[j]);
            float4 v = make_float4(lo.x, lo.y, hi.x, hi.y);
            *(float4*)&d_xg[(size_t)(pbase+pl)*XG_STRIDE + b*G_SZ + 4*gx] = v;
        }
    }
}

// ============================================================
// Kernel 2: LSTM scan (216 steps) + final FC.
// tanh.approx.f32 activations; 2-way split FMA trees.
// ============================================================
__global__ void __launch_bounds__(128) lstm_kernel(const float* __restrict__ whh,  // [40][10]
                                                   const float* __restrict__ fcw,  // [2][10]
                                                   const float* __restrict__ fcb,
                                                   float* __restrict__ out)
{
    int warp = threadIdx.x >> 5;
    int lid  = threadIdx.x & 31;
    int b    = blockIdx.x*4 + warp;

    int r = min(lid, 19);
    float wa[H_SZ], wb[H_SZ];
    #pragma unroll
    for (int j = 0; j < H_SZ; j++) {
        wa[j] = whh[r*H_SZ + j];
        wb[j] = whh[(r+20)*H_SZ + j];
    }
    // act2: lanes<10 -> tanh(g2); lanes 10..19 -> sigmoid(g2)=0.5*tanh(0.5*g2)+0.5
    const float sc2 = (lid < 10) ? 1.0f : 0.5f;
    const float k1  = (lid < 10) ? 1.0f : 0.5f;
    const float k0  = (lid < 10) ? 0.0f : 0.5f;

    float h[H_SZ];
    #pragma unroll
    for (int j = 0; j < H_SZ; j++) h[j] = 0.f;
    float c = 0.f;

    const float* xp = d_xg + (size_t)b*G_SZ + r;
    float p1 = __ldg(xp);
    float p2 = __ldg(xp + 20);

    for (int t = 0; t < L_SZ; t++) {
        float cur1 = p1, cur2 = p2;
        if (t < L_SZ-1) {
            const float* nx = xp + (size_t)(t+1)*XG_STRIDE;
            p1 = __ldg(nx);
            p2 = __ldg(nx + 20);
        }
        // two 5-deep chains per gate, then combine
        float s1a = cur1, s1b = 0.f, s2a = cur2, s2b = 0.f;
        #pragma unroll
        for (int j = 0; j < 5; j++) {
            s1a = fmaf(wa[j],   h[j],   s1a);
            s1b = fmaf(wa[j+5], h[j+5], s1b);
            s2a = fmaf(wb[j],   h[j],   s2a);
            s2b = fmaf(wb[j+5], h[j+5], s2b);
        }
        float g1 = s1a + s1b;
        float g2 = s2a + s2b;
        float a1 = fmaf(0.5f, tanh_a(0.5f*g1), 0.5f);   // sigmoid: i (l<10) / f (10..19)
        float a2 = fmaf(k1,   tanh_a(sc2*g2),  k0);     // tanh g (l<10) / sigmoid o (10..19)
        float fv = __shfl_sync(0xffffffffu, a1, lid + 10);
        float ov = __shfl_sync(0xffffffffu, a2, lid + 10);
        c = fmaf(fv, c, a1*a2);                         // valid on lanes<10
        float hv = ov * tanh_a(c);
        #pragma unroll
        for (int j = 0; j < H_SZ; j++)
            h[j] = __shfl_sync(0xffffffffu, hv, j);
    }

    if (lid < 2) {
        float o = fcb[lid];
        #pragma unroll
        for (int j = 0; j < H_SZ; j++) o = fmaf(fcw[lid*H_SZ + j], h[j], o);
        out[b*2 + lid] = o;
    }
}

// ============================================================
extern "C" void kernel_launch(void* const* d_in, const int* in_sizes, int n_in,
                              void* d_out, int out_size)
{
    const float* x     = (const float*)d_in[0];
    const float* ctw   = (const float*)d_in[1];
    const float* ctb   = (const float*)d_in[2];
    const float* csw   = (const float*)d_in[3];
    const float* gamma = (const float*)d_in[4];
    const float* beta  = (const float*)d_in[5];
    const float* mean  = (const float*)d_in[6];
    const float* var   = (const float*)d_in[7];
    const float* wih   = (const float*)d_in[8];
    const float* whh   = (const float*)d_in[9];
    const float* bih   = (const float*)d_in[10];
    const float* bhh   = (const float*)d_in[11];
    const float* fcw   = (const float*)d_in[12];
    const float* fcb   = (const float*)d_in[13];
    float* out = (float*)d_out;

    prep_kernel<<<PREP_CTAS, 256>>>(ctw, ctb, csw, gamma, beta, mean, var, wih, bih, bhh);
    conv_kernel<<<dim3(2, B_SZ), dim3(10, 25)>>>(x);
    lstm_kernel<<<B_SZ/4, 128>>>(whh, fcw, fcb, out);
}